// round 1
// baseline (speedup 1.0000x reference)
#include <cuda_runtime.h>

#define NNODES 16384
#define NFEAT  300
#define NHID   512
#define NOUT   256
#define NACT   64
#define NEIGH  2048
#define SS     2112      // NACT + NEIGH
#define MAXNNZ 64

// ---- scratch (static device globals; no runtime allocation) ----
__device__ int   g_cur[SS];
__device__ int   g_nnz[SS];
__device__ int   g_cols[SS * MAXNNZ];
__device__ float g_XW1[SS * NHID];     // x[cur] @ W1
__device__ float g_w[NHID];            // W2 @ imp_w
__device__ float g_u[SS];              // relu(A @ XW1) @ w

__device__ __forceinline__ float warp_sum(float v) {
    #pragma unroll
    for (int o = 16; o > 0; o >>= 1) v += __shfl_xor_sync(0xFFFFFFFFu, v, o);
    return v;
}

// cur = concat(active_idx, neighbor_idx)
__global__ void k_build_cur(const int* __restrict__ act, const int* __restrict__ nb) {
    int t = blockIdx.x * blockDim.x + threadIdx.x;
    if (t < SS) g_cur[t] = (t < NACT) ? act[t] : nb[t - NACT];
}

// sparse extraction of a_sub = adj[cur][:, cur]; entries are exactly 0/1,
// so we only record column indices (within the subgraph) per row.
__global__ void k_extract(const float* __restrict__ adj) {
    __shared__ int s_cur[SS];
    __shared__ int s_cols[MAXNNZ];
    __shared__ int s_cnt;
    int tid = threadIdx.x;
    for (int j = tid; j < SS; j += blockDim.x) s_cur[j] = g_cur[j];
    if (tid == 0) s_cnt = 0;
    __syncthreads();
    const float* row = adj + (size_t)g_cur[blockIdx.x] * NNODES;
    for (int j = tid; j < SS; j += blockDim.x) {
        if (row[s_cur[j]] != 0.0f) {
            int k = atomicAdd(&s_cnt, 1);
            if (k < MAXNNZ) s_cols[k] = j;
        }
    }
    __syncthreads();
    int n = min(s_cnt, MAXNNZ);
    if (tid == 0) g_nnz[blockIdx.x] = n;
    if (tid < n) g_cols[blockIdx.x * MAXNNZ + tid] = s_cols[tid];
}

// g_w = W2 @ imp_w   (one warp per output row of W2 [NHID, NOUT])
__global__ void k_w(const float* __restrict__ W2, const float* __restrict__ iw) {
    int warp = (blockIdx.x * blockDim.x + threadIdx.x) >> 5;
    int lane = threadIdx.x & 31;
    if (warp >= NHID) return;
    const float* row = W2 + (size_t)warp * NOUT;
    float s = 0.f;
    for (int c = lane; c < NOUT; c += 32) s += row[c] * iw[c];
    s = warp_sum(s);
    if (lane == 0) g_w[warp] = s;
}

// g_XW1[SS, NHID] = x[g_cur][SS, NFEAT] @ W1[NFEAT, NHID]
// 64x64 block tile, BK=16, 256 threads, 4x4 register tile per thread.
__global__ void k_gemm_gather(const float* __restrict__ X, const float* __restrict__ B) {
    const int K = NFEAT, Nn = NHID;
    __shared__ float As[16][64];
    __shared__ float Bs[16][68];
    int tid = threadIdx.x;
    int tx = tid & 15, ty = tid >> 4;
    int bm = blockIdx.y * 64, bn = blockIdx.x * 64;
    float acc[4][4] = {};
    int arow[4];
    #pragma unroll
    for (int t = 0; t < 4; t++) {
        int r = (tid + t * 256) >> 4;
        arow[t] = g_cur[bm + r];
    }
    for (int k0 = 0; k0 < K; k0 += 16) {
        #pragma unroll
        for (int t = 0; t < 4; t++) {
            int l = tid + t * 256;
            int r = l >> 4, c = l & 15;
            float a = 0.f;
            if (k0 + c < K) a = X[(size_t)arow[t] * K + k0 + c];
            As[c][r] = a;
        }
        #pragma unroll
        for (int t = 0; t < 4; t++) {
            int l = tid + t * 256;
            int r = l >> 6, c = l & 63;
            float b = 0.f;
            if (k0 + r < K) b = B[(size_t)(k0 + r) * Nn + bn + c];
            Bs[r][c] = b;
        }
        __syncthreads();
        #pragma unroll
        for (int k = 0; k < 16; k++) {
            float a[4], b[4];
            #pragma unroll
            for (int i = 0; i < 4; i++) a[i] = As[k][ty * 4 + i];
            #pragma unroll
            for (int j = 0; j < 4; j++) b[j] = Bs[k][tx * 4 + j];
            #pragma unroll
            for (int i = 0; i < 4; i++)
                #pragma unroll
                for (int j = 0; j < 4; j++) acc[i][j] += a[i] * b[j];
        }
        __syncthreads();
    }
    #pragma unroll
    for (int i = 0; i < 4; i++) {
        int rr = bm + ty * 4 + i;
        #pragma unroll
        for (int j = 0; j < 4; j++)
            g_XW1[(size_t)rr * Nn + bn + tx * 4 + j] = acc[i][j];
    }
}

// fused: h1_row = relu(sum over sparse row of XW1);  g_u[i] = dot(h1_row, g_w)
// one block (256 threads) per subgraph row; XW1 is L2-resident (4.3 MB).
__global__ void k_layer2() {
    __shared__ float s_w[NHID];
    __shared__ float s_red[8];
    int i = blockIdx.x, tid = threadIdx.x;
    s_w[tid] = g_w[tid];
    s_w[tid + 256] = g_w[tid + 256];
    __syncthreads();
    int nnz = g_nnz[i];
    const int* cp = g_cols + i * MAXNNZ;
    float a0 = 0.f, a1 = 0.f;
    for (int k = 0; k < nnz; k++) {
        const float* src = g_XW1 + (size_t)cp[k] * NHID;
        a0 += src[tid];
        a1 += src[tid + 256];
    }
    float p = fmaxf(a0, 0.f) * s_w[tid] + fmaxf(a1, 0.f) * s_w[tid + 256];
    p = warp_sum(p);
    if ((tid & 31) == 0) s_red[tid >> 5] = p;
    __syncthreads();
    if (tid == 0) {
        float s = 0.f;
        #pragma unroll
        for (int w = 0; w < 8; w++) s += s_red[w];
        g_u[i] = s;
    }
}

// single block: v = A@u; imp = A@v + b; L1-normalize; write outputs.
__global__ void k_finalize(const float* __restrict__ impb, const int* __restrict__ nb,
                           float* __restrict__ out, int out_size) {
    __shared__ float s_v[SS];
    __shared__ float s_imp[SS];
    __shared__ float s_red[32];
    __shared__ float s_tot;
    int tid = threadIdx.x;
    for (int i = tid; i < SS; i += 1024) {
        int nnz = g_nnz[i];
        const int* cp = g_cols + i * MAXNNZ;
        float a = 0.f;
        for (int k = 0; k < nnz; k++) a += g_u[cp[k]];
        s_v[i] = a;
    }
    __syncthreads();
    float b = impb[0];
    float part = 0.f;
    for (int i = tid; i < SS; i += 1024) {
        int nnz = g_nnz[i];
        const int* cp = g_cols + i * MAXNNZ;
        float a = b;
        for (int k = 0; k < nnz; k++) a += s_v[cp[k]];
        s_imp[i] = a;
        part += fabsf(a);
    }
    part = warp_sum(part);
    if ((tid & 31) == 0) s_red[tid >> 5] = part;
    __syncthreads();
    if (tid == 0) {
        float s = 0.f;
        #pragma unroll
        for (int w = 0; w < 32; w++) s += s_red[w];
        s_tot = s;
    }
    __syncthreads();
    float inv = 1.f / fmaxf(s_tot, 1e-12f);
    for (int j = tid; j < NEIGH; j += 1024) out[j] = s_imp[NACT + j] * inv;
    if (out_size >= 2 * NEIGH)
        for (int j = tid; j < NEIGH; j += 1024) out[NEIGH + j] = (float)nb[j];
}

extern "C" void kernel_launch(void* const* d_in, const int* in_sizes, int n_in,
                              void* d_out, int out_size) {
    const float* x   = (const float*)d_in[0];
    const float* adj = (const float*)d_in[1];
    const int*   act = (const int*)d_in[2];
    const int*   nb  = (const int*)d_in[3];
    const float* W1  = (const float*)d_in[4];
    const float* W2  = (const float*)d_in[5];
    const float* iw  = (const float*)d_in[6];
    const float* ib  = (const float*)d_in[7];
    float* out = (float*)d_out;
    (void)in_sizes; (void)n_in;

    k_build_cur<<<(SS + 255) / 256, 256>>>(act, nb);
    k_w<<<(NHID * 32) / 256, 256>>>(W2, iw);
    k_gemm_gather<<<dim3(NHID / 64, SS / 64), 256>>>(x, W1);
    k_extract<<<SS, 256>>>(adj);
    k_layer2<<<SS, 256>>>();
    k_finalize<<<1, 1024>>>(ib, nb, out, out_size);
}

// round 4
// speedup vs baseline: 1.0522x; 1.0522x over previous
#include <cuda_runtime.h>

#define NNODES 16384
#define NFEAT  300
#define NHID   512
#define NOUT   256
#define NACT   64
#define NEIGH  2048
#define SS     2112      // NACT + NEIGH
#define MAXNNZ 64

#define GEMM_BLOCKS   264            // (NHID/64) * (SS/64) = 8 * 33
#define EXTRACT_BLOCKS SS
#define MAIN_BLOCKS   (GEMM_BLOCKS + EXTRACT_BLOCKS)   // 2376 = 264 * 9

// ---- scratch (static device globals; no runtime allocation) ----
__device__ int   g_cur[SS];
__device__ int   g_lo[NNODES];        // min subgraph index j with cur[j]==v (INT_MAX if none)
__device__ int   g_hi[NNODES];        // max subgraph index j with cur[j]==v (-1 if none)
__device__ int   g_nnz[SS];
__device__ int   g_cols[SS * MAXNNZ];
__device__ float g_XW1[SS * NHID];    // x[cur] @ W1
__device__ float g_w[NHID];           // W2 @ imp_w
__device__ float g_u[SS];             // relu(A @ XW1) @ w

__device__ __forceinline__ float warp_sum(float v) {
    #pragma unroll
    for (int o = 16; o > 0; o >>= 1) v += __shfl_xor_sync(0xFFFFFFFFu, v, o);
    return v;
}

// prep1: init g_lo/g_hi, build g_cur, compute g_w = W2 @ imp_w
__global__ void k_prep1(const int* __restrict__ act, const int* __restrict__ nb,
                        const float* __restrict__ W2, const float* __restrict__ iw) {
    int t = blockIdx.x * blockDim.x + threadIdx.x;     // 0 .. 16383
    if (t < NNODES) { g_lo[t] = 0x7fffffff; g_hi[t] = -1; }
    if (t < SS)     g_cur[t] = (t < NACT) ? act[t] : nb[t - NACT];
    int warp = t >> 5, lane = t & 31;
    if (warp < NHID) {
        const float* row = W2 + (size_t)warp * NOUT;
        float s = 0.f;
        for (int c = lane; c < NOUT; c += 32) s += row[c] * iw[c];
        s = warp_sum(s);
        if (lane == 0) g_w[warp] = s;
    }
}

// prep2: scatter inverse map (handles wrap-pad duplicates: each node appears <=2x)
__global__ void k_prep2() {
    int j = blockIdx.x * blockDim.x + threadIdx.x;
    if (j < SS) {
        int v = g_cur[j];
        atomicMin(&g_lo[v], j);
        atomicMax(&g_hi[v], j);
    }
}

// ---------------------------------------------------------------------------
// fused main kernel: block-role specialization.
//   bid % 9 == 0  -> GEMM tile block  (264 blocks):  g_XW1 = x[cur] @ W1
//   otherwise     -> extract block    (2112 blocks): sparse row of adj[cur][:,cur]
// ---------------------------------------------------------------------------
__global__ void __launch_bounds__(256) k_main(const float* __restrict__ X,
                                              const float* __restrict__ B,
                                              const float* __restrict__ adj) {
    int bid = blockIdx.x;
    int tid = threadIdx.x;

    if (bid % 9 == 0) {
        // ================= GEMM path =================
        int gidx = bid / 9;                 // 0..263
        int bn = (gidx & 7) * 64;           // NHID tile
        int bm = (gidx >> 3) * 64;          // row tile
        __shared__ float As[16][64];
        __shared__ float Bs[16][68];
        int tx = tid & 15, ty = tid >> 4;

        // A-load mapping: thread -> (row r, float4 chunk c4 along k)
        int ar = tid >> 2;                  // 0..63
        int ac4 = tid & 3;                  // 0..3  (k-offset = ac4*4)
        int arow = g_cur[bm + ar];
        const float* Arowp = X + (size_t)arow * NFEAT;

        // B-load mapping: thread -> (k-row br, float4 chunk bc4)
        int br = tid >> 4;                  // 0..15
        int bc4 = tid & 15;                 // 0..15

        float acc[4][4] = {};
        for (int k0 = 0; k0 < NFEAT; k0 += 16) {
            // load A tile (transposed into As[k][m])
            float4 av = make_float4(0.f, 0.f, 0.f, 0.f);
            int ak = k0 + ac4 * 4;
            if (ak < NFEAT) av = *(const float4*)(Arowp + ak);   // NFEAT%4==0: full or none
            As[ac4 * 4 + 0][ar] = av.x;
            As[ac4 * 4 + 1][ar] = av.y;
            As[ac4 * 4 + 2][ar] = av.z;
            As[ac4 * 4 + 3][ar] = av.w;
            // load B tile
            float4 bv = make_float4(0.f, 0.f, 0.f, 0.f);
            if (k0 + br < NFEAT) bv = *(const float4*)(B + (size_t)(k0 + br) * NHID + bn + bc4 * 4);
            *(float4*)&Bs[br][bc4 * 4] = bv;
            __syncthreads();
            #pragma unroll
            for (int k = 0; k < 16; k++) {
                float4 a = *(const float4*)&As[k][ty * 4];
                float4 b = *(const float4*)&Bs[k][tx * 4];
                float ae[4] = {a.x, a.y, a.z, a.w};
                float be[4] = {b.x, b.y, b.z, b.w};
                #pragma unroll
                for (int i = 0; i < 4; i++)
                    #pragma unroll
                    for (int j = 0; j < 4; j++) acc[i][j] += ae[i] * be[j];
            }
            __syncthreads();
        }
        #pragma unroll
        for (int i = 0; i < 4; i++) {
            int rr = bm + ty * 4 + i;
            #pragma unroll
            for (int j = 0; j < 4; j++)
                g_XW1[(size_t)rr * NHID + bn + tx * 4 + j] = acc[i][j];
        }
    } else {
        // ================= extract path: stream one full adjacency row =========
        int i = bid - bid / 9 - 1;          // 0..2111
        __shared__ int s_cols[MAXNNZ];
        __shared__ int s_sorted[MAXNNZ];
        __shared__ int s_cnt;
        if (tid == 0) s_cnt = 0;
        __syncthreads();
        const float4* row = (const float4*)(adj + (size_t)g_cur[i] * NNODES);
        #pragma unroll 2
        for (int it = 0; it < NNODES / 4 / 256; it++) {
            int p = it * 256 + tid;                     // float4 index
            float4 v = __ldcs(row + p);                 // evict-first streaming
            if (v.x != 0.f || v.y != 0.f || v.z != 0.f || v.w != 0.f) {
                float e[4] = {v.x, v.y, v.z, v.w};
                #pragma unroll
                for (int q = 0; q < 4; q++) {
                    if (e[q] != 0.f) {
                        int col = p * 4 + q;
                        int lo = g_lo[col];
                        if (lo < SS) {                  // col is in subgraph
                            int k = atomicAdd(&s_cnt, 1);
                            if (k < MAXNNZ) s_cols[k] = lo;
                            int hi = g_hi[col];
                            if (hi != lo) {             // wrap-pad duplicate column
                                k = atomicAdd(&s_cnt, 1);
                                if (k < MAXNNZ) s_cols[k] = hi;
                            }
                        }
                    }
                }
            }
        }
        __syncthreads();
        int n = min(s_cnt, MAXNNZ);
        // rank-sort for deterministic downstream summation order
        if (tid < n) {
            int val = s_cols[tid];
            int rank = 0;
            for (int k = 0; k < n; k++) rank += (s_cols[k] < val);
            s_sorted[rank] = val;
        }
        __syncthreads();
        if (tid == 0) g_nnz[i] = n;
        if (tid < n) g_cols[i * MAXNNZ + tid] = s_sorted[tid];
    }
}

// fused layer2: h1_row = relu(sum over sparse row of XW1); g_u[i] = dot(h1_row, g_w)
__global__ void k_layer2() {
    __shared__ float s_w[NHID];
    __shared__ float s_red[8];
    int i = blockIdx.x, tid = threadIdx.x;
    s_w[tid] = g_w[tid];
    s_w[tid + 256] = g_w[tid + 256];
    __syncthreads();
    int nnz = g_nnz[i];
    const int* cp = g_cols + i * MAXNNZ;
    float a0 = 0.f, a1 = 0.f;
    for (int k = 0; k < nnz; k++) {
        const float* src = g_XW1 + (size_t)cp[k] * NHID;
        a0 += src[tid];
        a1 += src[tid + 256];
    }
    float p = fmaxf(a0, 0.f) * s_w[tid] + fmaxf(a1, 0.f) * s_w[tid + 256];
    p = warp_sum(p);
    if ((tid & 31) == 0) s_red[tid >> 5] = p;
    __syncthreads();
    if (tid == 0) {
        float s = 0.f;
        #pragma unroll
        for (int w = 0; w < 8; w++) s += s_red[w];
        g_u[i] = s;
    }
}

// single block: v = A@u; imp = A@v + b; L1-normalize; write outputs.
__global__ void k_finalize(const float* __restrict__ impb, const int* __restrict__ nb,
                           float* __restrict__ out, int out_size) {
    __shared__ float s_v[SS];
    __shared__ float s_imp[SS];
    __shared__ float s_red[32];
    __shared__ float s_tot;
    int tid = threadIdx.x;
    for (int i = tid; i < SS; i += 1024) {
        int nnz = g_nnz[i];
        const int* cp = g_cols + i * MAXNNZ;
        float a = 0.f;
        for (int k = 0; k < nnz; k++) a += g_u[cp[k]];
        s_v[i] = a;
    }
    __syncthreads();
    float b = impb[0];
    float part = 0.f;
    for (int i = tid; i < SS; i += 1024) {
        int nnz = g_nnz[i];
        const int* cp = g_cols + i * MAXNNZ;
        float a = b;
        for (int k = 0; k < nnz; k++) a += s_v[cp[k]];
        s_imp[i] = a;
        part += fabsf(a);
    }
    part = warp_sum(part);
    if ((tid & 31) == 0) s_red[tid >> 5] = part;
    __syncthreads();
    if (tid == 0) {
        float s = 0.f;
        #pragma unroll
        for (int w = 0; w < 32; w++) s += s_red[w];
        s_tot = s;
    }
    __syncthreads();
    float inv = 1.f / fmaxf(s_tot, 1e-12f);
    for (int j = tid; j < NEIGH; j += 1024) out[j] = s_imp[NACT + j] * inv;
    if (out_size >= 2 * NEIGH)
        for (int j = tid; j < NEIGH; j += 1024) out[NEIGH + j] = (float)nb[j];
}

extern "C" void kernel_launch(void* const* d_in, const int* in_sizes, int n_in,
                              void* d_out, int out_size) {
    const float* x   = (const float*)d_in[0];
    const float* adj = (const float*)d_in[1];
    const int*   act = (const int*)d_in[2];
    const int*   nb  = (const int*)d_in[3];
    const float* W1  = (const float*)d_in[4];
    const float* W2  = (const float*)d_in[5];
    const float* iw  = (const float*)d_in[6];
    const float* ib  = (const float*)d_in[7];
    float* out = (float*)d_out;
    (void)in_sizes; (void)n_in;

    k_prep1<<<(NNODES + 255) / 256, 256>>>(act, nb, W2, iw);
    k_prep2<<<(SS + 255) / 256, 256>>>();
    k_main<<<MAIN_BLOCKS, 256>>>(x, W1, adj);
    k_layer2<<<SS, 256>>>();
    k_finalize<<<1, 1024>>>(ib, nb, out, out_size);
}

// round 5
// speedup vs baseline: 1.2443x; 1.1825x over previous
#include <cuda_runtime.h>
#include <cstdint>

#define NNODES 16384
#define NFEAT  300
#define NHID   512
#define NOUT   256
#define NACT   64
#define NEIGH  2048
#define SS     2112      // NACT + NEIGH
#define MAXNNZ 64

#define GEMM_BLOCKS 264                       // 33 row-tiles x 8 col-tiles of 64
#define MAIN_BLOCKS (GEMM_BLOCKS + SS)        // 2376 = 264 * 9

// ---- scratch (static device globals; zero-initialized at module load) ----
__device__ int   g_loE[NNODES];    // atomicMax of (SS - j); 0 = absent; lo = SS - val
__device__ int   g_hiE[NNODES];    // atomicMax of (j + 1);  0 = absent; hi = val - 1
__device__ int   g_nnz[SS];
__device__ int   g_cols[SS * MAXNNZ];
__device__ float g_XW1[SS * NHID]; // x[cur] @ W1
__device__ float g_w[NHID];        // W2 @ imp_w
__device__ float g_u[SS];          // relu(A @ XW1) @ w

__device__ __forceinline__ float warp_sum(float v) {
    #pragma unroll
    for (int o = 16; o > 0; o >>= 1) v += __shfl_xor_sync(0xFFFFFFFFu, v, o);
    return v;
}

__device__ __forceinline__ uint32_t f2tf(float x) {
    uint32_t r;
    asm("cvt.rna.tf32.f32 %0, %1;" : "=r"(r) : "f"(x));
    return r;
}

__device__ __forceinline__ void mma_tf32(float* d, const uint32_t* a, const uint32_t* b) {
    asm volatile(
        "mma.sync.aligned.m16n8k8.row.col.f32.tf32.tf32.f32 "
        "{%0,%1,%2,%3},{%4,%5,%6,%7},{%8,%9},{%0,%1,%2,%3};"
        : "+f"(d[0]), "+f"(d[1]), "+f"(d[2]), "+f"(d[3])
        : "r"(a[0]), "r"(a[1]), "r"(a[2]), "r"(a[3]), "r"(b[0]), "r"(b[1]));
}

// prep: scatter inverse map (idempotent atomicMax on zero-init arrays — replay-safe)
//       + g_w = W2 @ imp_w.  16384 threads.
__global__ void k_prep(const int* __restrict__ act, const int* __restrict__ nb,
                       const float* __restrict__ W2, const float* __restrict__ iw) {
    int t = blockIdx.x * blockDim.x + threadIdx.x;
    if (t < SS) {
        int v = (t < NACT) ? act[t] : nb[t - NACT];
        atomicMax(&g_loE[v], SS - t);
        atomicMax(&g_hiE[v], t + 1);
    }
    int warp = t >> 5, lane = t & 31;
    if (warp < NHID) {
        const float* row = W2 + (size_t)warp * NOUT;
        float s = 0.f;
        for (int c = lane; c < NOUT; c += 32) s += row[c] * iw[c];
        s = warp_sum(s);
        if (lane == 0) g_w[warp] = s;
    }
}

// ---------------------------------------------------------------------------
// fused main kernel:
//   bid % 9 == 0 -> tf32 tensor-core GEMM tile (264 blocks): g_XW1 = x[cur] @ W1
//   otherwise    -> extract block (2112): sparse row of adj[cur][:,cur]
// ---------------------------------------------------------------------------
#define AS_STRIDE 36    // 32 + 4 pad: conflict-free A-frag loads
#define BS_STRIDE 72    // 64 + 8 pad: conflict-free B-frag loads
#define SMEM_BYTES (64 * AS_STRIDE * 4 + 32 * BS_STRIDE * 4)   // 9216 + 9216

__global__ void __launch_bounds__(256) k_main(const float* __restrict__ X,
                                              const float* __restrict__ W1,
                                              const float* __restrict__ adj,
                                              const int* __restrict__ act,
                                              const int* __restrict__ nb) {
    __shared__ __align__(16) char smem_raw[SMEM_BYTES];
    int bid = blockIdx.x;
    int tid = threadIdx.x;

    if (bid % 9 == 0) {
        // ================= tf32 MMA GEMM path =================
        int gidx = bid / 9;                 // 0..263
        int bm = (gidx >> 3) * 64;          // 33 row tiles
        int bn = (gidx & 7) * 64;           // 8 col tiles
        uint32_t* As = (uint32_t*)smem_raw;                 // [64][AS_STRIDE] tf32
        uint32_t* Bs = As + 64 * AS_STRIDE;                 // [32][BS_STRIDE] tf32
        int warp = tid >> 5, lane = tid & 31;
        int wr = warp >> 2;                 // 0..1 : 32-row slab
        int wc = warp & 3;                  // 0..3 : 16-col slab

        float acc[2][2][4] = {};            // (ti 16-row, tj 8-col) m16n8 frags

        for (int k0 = 0; k0 < NFEAT; k0 += 32) {
            // stage A: 64 rows x 32 k (tf32), gathered rows of X
            #pragma unroll
            for (int r = 0; r < 2; r++) {
                int f = tid + r * 256;          // 0..511
                int m = f >> 3, c4 = f & 7;
                int k = k0 + c4 * 4;
                float4 v = make_float4(0.f, 0.f, 0.f, 0.f);
                if (k < NFEAT) {
                    int gr = bm + m;
                    int node = (gr < NACT) ? act[gr] : nb[gr - NACT];
                    v = *(const float4*)(X + (size_t)node * NFEAT + k);
                }
                uint4 u = make_uint4(f2tf(v.x), f2tf(v.y), f2tf(v.z), f2tf(v.w));
                *(uint4*)&As[m * AS_STRIDE + c4 * 4] = u;
            }
            // stage B: 32 k x 64 cols (tf32)
            #pragma unroll
            for (int r = 0; r < 2; r++) {
                int f = tid + r * 256;          // 0..511
                int kr = f >> 4, c4 = f & 15;
                int k = k0 + kr;
                float4 v = make_float4(0.f, 0.f, 0.f, 0.f);
                if (k < NFEAT) v = *(const float4*)(W1 + (size_t)k * NHID + bn + c4 * 4);
                uint4 u = make_uint4(f2tf(v.x), f2tf(v.y), f2tf(v.z), f2tf(v.w));
                *(uint4*)&Bs[kr * BS_STRIDE + c4 * 4] = u;
            }
            __syncthreads();
            #pragma unroll
            for (int kk = 0; kk < 32; kk += 8) {
                uint32_t a[2][4], b[2][2];
                #pragma unroll
                for (int ti = 0; ti < 2; ti++) {
                    int r0 = wr * 32 + ti * 16 + (lane >> 2);
                    int kc = kk + (lane & 3);
                    a[ti][0] = As[r0 * AS_STRIDE + kc];
                    a[ti][1] = As[(r0 + 8) * AS_STRIDE + kc];
                    a[ti][2] = As[r0 * AS_STRIDE + kc + 4];
                    a[ti][3] = As[(r0 + 8) * AS_STRIDE + kc + 4];
                }
                #pragma unroll
                for (int tj = 0; tj < 2; tj++) {
                    int col = wc * 16 + tj * 8 + (lane >> 2);
                    int kc = kk + (lane & 3);
                    b[tj][0] = Bs[kc * BS_STRIDE + col];
                    b[tj][1] = Bs[(kc + 4) * BS_STRIDE + col];
                }
                #pragma unroll
                for (int ti = 0; ti < 2; ti++)
                    #pragma unroll
                    for (int tj = 0; tj < 2; tj++)
                        mma_tf32(acc[ti][tj], a[ti], b[tj]);
            }
            __syncthreads();
        }
        // epilogue
        int lane4 = (tid & 31) >> 2, lm = (tid & 3) * 2;
        #pragma unroll
        for (int ti = 0; ti < 2; ti++) {
            int row0 = bm + wr * 32 + ti * 16 + lane4;
            #pragma unroll
            for (int tj = 0; tj < 2; tj++) {
                int col0 = bn + wc * 16 + tj * 8 + lm;
                float* c = acc[ti][tj];
                *(float2*)&g_XW1[(size_t)row0 * NHID + col0]       = make_float2(c[0], c[1]);
                *(float2*)&g_XW1[(size_t)(row0 + 8) * NHID + col0] = make_float2(c[2], c[3]);
            }
        }
    } else {
        // ================= extract path: stream one adjacency row =================
        int i = bid - bid / 9 - 1;          // 0..2111
        int* s_cols   = (int*)smem_raw;
        int* s_sorted = s_cols + MAXNNZ;
        int* s_cntp   = s_sorted + MAXNNZ;
        if (tid == 0) *s_cntp = 0;
        __syncthreads();
        int node = (i < NACT) ? act[i] : nb[i - NACT];
        const float4* row = (const float4*)(adj + (size_t)node * NNODES);
        #pragma unroll 4
        for (int it = 0; it < NNODES / 4 / 256; it++) {
            int p = it * 256 + tid;
            float4 v = __ldcs(row + p);
            if (v.x != 0.f || v.y != 0.f || v.z != 0.f || v.w != 0.f) {
                float e[4] = {v.x, v.y, v.z, v.w};
                #pragma unroll
                for (int q = 0; q < 4; q++) {
                    if (e[q] != 0.f) {
                        int col = p * 4 + q;
                        int lov = g_loE[col];
                        if (lov > 0) {                     // col in subgraph
                            int lo = SS - lov;
                            int k = atomicAdd(s_cntp, 1);
                            if (k < MAXNNZ) s_cols[k] = lo;
                            int hi = g_hiE[col] - 1;
                            if (hi != lo) {                // wrap-pad duplicate
                                k = atomicAdd(s_cntp, 1);
                                if (k < MAXNNZ) s_cols[k] = hi;
                            }
                        }
                    }
                }
            }
        }
        __syncthreads();
        int n = min(*s_cntp, MAXNNZ);
        if (tid < n) {                       // rank-sort (values distinct)
            int val = s_cols[tid];
            int rank = 0;
            for (int k = 0; k < n; k++) rank += (s_cols[k] < val);
            s_sorted[rank] = val;
        }
        __syncthreads();
        if (tid == 0) g_nnz[i] = n;
        if (tid < n) g_cols[i * MAXNNZ + tid] = s_sorted[tid];
    }
}

// layer2: u[i] = relu(sum over sparse row of XW1) . w  — batched gathers for MLP
__global__ void k_layer2() {
    __shared__ float s_w[NHID];
    __shared__ float s_red[8];
    int i = blockIdx.x, tid = threadIdx.x;
    s_w[tid] = g_w[tid];
    s_w[tid + 256] = g_w[tid + 256];
    __syncthreads();
    int nnz = g_nnz[i];
    const int* cp = g_cols + i * MAXNNZ;
    float a0 = 0.f, a1 = 0.f;
    for (int k0 = 0; k0 < nnz; k0 += 8) {
        float v0[8], v1[8];
        #pragma unroll
        for (int q = 0; q < 8; q++) {
            float x0 = 0.f, x1 = 0.f;
            int kk = k0 + q;
            if (kk < nnz) {
                const float* s = g_XW1 + (size_t)cp[kk] * NHID;
                x0 = s[tid];
                x1 = s[tid + 256];
            }
            v0[q] = x0; v1[q] = x1;
        }
        #pragma unroll
        for (int q = 0; q < 8; q++) { a0 += v0[q]; a1 += v1[q]; }
    }
    float p = fmaxf(a0, 0.f) * s_w[tid] + fmaxf(a1, 0.f) * s_w[tid + 256];
    p = warp_sum(p);
    if ((tid & 31) == 0) s_red[tid >> 5] = p;
    __syncthreads();
    if (tid == 0) {
        float s = 0.f;
        #pragma unroll
        for (int w = 0; w < 8; w++) s += s_red[w];
        g_u[i] = s;
    }
}

// single block: v = A@u; imp = A@v + b; L1-normalize; write outputs.
__global__ void k_finalize(const float* __restrict__ impb, const int* __restrict__ nb,
                           float* __restrict__ out, int out_size) {
    __shared__ float s_v[SS];
    __shared__ float s_imp[SS];
    __shared__ float s_red[32];
    __shared__ float s_tot;
    int tid = threadIdx.x;
    for (int i = tid; i < SS; i += 1024) {
        int nnz = g_nnz[i];
        const int* cp = g_cols + i * MAXNNZ;
        float a = 0.f;
        for (int k = 0; k < nnz; k++) a += g_u[cp[k]];
        s_v[i] = a;
    }
    __syncthreads();
    float b = impb[0];
    float part = 0.f;
    for (int i = tid; i < SS; i += 1024) {
        int nnz = g_nnz[i];
        const int* cp = g_cols + i * MAXNNZ;
        float a = b;
        for (int k = 0; k < nnz; k++) a += s_v[cp[k]];
        s_imp[i] = a;
        part += fabsf(a);
    }
    part = warp_sum(part);
    if ((tid & 31) == 0) s_red[tid >> 5] = part;
    __syncthreads();
    if (tid == 0) {
        float s = 0.f;
        #pragma unroll
        for (int w = 0; w < 32; w++) s += s_red[w];
        s_tot = s;
    }
    __syncthreads();
    float inv = 1.f / fmaxf(s_tot, 1e-12f);
    for (int j = tid; j < NEIGH; j += 1024) out[j] = s_imp[NACT + j] * inv;
    if (out_size >= 2 * NEIGH)
        for (int j = tid; j < NEIGH; j += 1024) out[NEIGH + j] = (float)nb[j];
}

extern "C" void kernel_launch(void* const* d_in, const int* in_sizes, int n_in,
                              void* d_out, int out_size) {
    const float* x   = (const float*)d_in[0];
    const float* adj = (const float*)d_in[1];
    const int*   act = (const int*)d_in[2];
    const int*   nb  = (const int*)d_in[3];
    const float* W1  = (const float*)d_in[4];
    const float* W2  = (const float*)d_in[5];
    const float* iw  = (const float*)d_in[6];
    const float* ib  = (const float*)d_in[7];
    float* out = (float*)d_out;
    (void)in_sizes; (void)n_in;

    k_prep<<<NNODES / 256, 256>>>(act, nb, W2, iw);
    k_main<<<MAIN_BLOCKS, 256>>>(x, W1, adj, act, nb);
    k_layer2<<<SS, 256>>>();
    k_finalize<<<1, 1024>>>(ib, nb, out, out_size);
}

// round 7
// speedup vs baseline: 1.3788x; 1.1081x over previous
#include <cuda_runtime.h>
#include <cstdint>

#define NNODES 16384
#define NFEAT  300
#define NHID   512
#define NOUT   256
#define NACT   64
#define NEIGH  2048
#define SS     2112      // NACT + NEIGH
#define MAXNNZ 64

#define GEMM_BLOCKS 264                       // 33 row-tiles x 8 col-tiles of 64
#define MAIN_BLOCKS (GEMM_BLOCKS + SS)        // 2376 = 264 * 9

// ---- scratch (static device globals; zero-initialized at module load) ----
__device__ int   g_loE[NNODES];    // atomicMax of (SS - j); 0 = absent; lo = SS - val
__device__ int   g_hiE[NNODES];    // atomicMax of (j + 1);  0 = absent; hi = val - 1
__device__ int   g_nnz[SS];
__device__ int   g_cols[SS * MAXNNZ];
__device__ float g_XW1[SS * NHID]; // x[cur] @ W1
__device__ float g_w[NHID];        // W2 @ imp_w
__device__ float g_u[SS];          // relu(A @ XW1) @ w

__device__ __forceinline__ float warp_sum(float v) {
    #pragma unroll
    for (int o = 16; o > 0; o >>= 1) v += __shfl_xor_sync(0xFFFFFFFFu, v, o);
    return v;
}

__device__ __forceinline__ uint32_t f2tf(float x) {
    uint32_t r;
    asm("cvt.rna.tf32.f32 %0, %1;" : "=r"(r) : "f"(x));
    return r;
}

__device__ __forceinline__ void mma_tf32(float* d, const uint32_t* a, const uint32_t* b) {
    asm volatile(
        "mma.sync.aligned.m16n8k8.row.col.f32.tf32.tf32.f32 "
        "{%0,%1,%2,%3},{%4,%5,%6,%7},{%8,%9},{%0,%1,%2,%3};"
        : "+f"(d[0]), "+f"(d[1]), "+f"(d[2]), "+f"(d[3])
        : "r"(a[0]), "r"(a[1]), "r"(a[2]), "r"(a[3]), "r"(b[0]), "r"(b[1]));
}

// prep: scatter inverse map (idempotent atomicMax on zero-init arrays — replay-safe)
//       + g_w = W2 @ imp_w.  16384 threads.
__global__ void k_prep(const int* __restrict__ act, const int* __restrict__ nb,
                       const float* __restrict__ W2, const float* __restrict__ iw) {
    int t = blockIdx.x * blockDim.x + threadIdx.x;
    if (t < SS) {
        int v = (t < NACT) ? act[t] : nb[t - NACT];
        atomicMax(&g_loE[v], SS - t);
        atomicMax(&g_hiE[v], t + 1);
    }
    int warp = t >> 5, lane = t & 31;
    if (warp < NHID) {
        const float* row = W2 + (size_t)warp * NOUT;
        float s = 0.f;
        for (int c = lane; c < NOUT; c += 32) s += row[c] * iw[c];
        s = warp_sum(s);
        if (lane == 0) g_w[warp] = s;
    }
}

// ---------------------------------------------------------------------------
// fused main kernel:
//   bid % 9 == 0 -> tf32 tensor-core GEMM tile (264 blocks): g_XW1 = x[cur] @ W1
//   otherwise    -> extract block (2112): sparse row of adj[cur][:,cur]
// ---------------------------------------------------------------------------
#define AS_STRIDE 36    // 32 + 4 pad: conflict-free A-frag loads
#define BS_STRIDE 72    // 64 + 8 pad: conflict-free B-frag loads
#define SMEM_BYTES (64 * AS_STRIDE * 4 + 32 * BS_STRIDE * 4)   // 9216 + 9216

__global__ void __launch_bounds__(256) k_main(const float* __restrict__ X,
                                              const float* __restrict__ W1,
                                              const float* __restrict__ adj,
                                              const int* __restrict__ act,
                                              const int* __restrict__ nb) {
    __shared__ __align__(16) char smem_raw[SMEM_BYTES];
    int bid = blockIdx.x;
    int tid = threadIdx.x;

    if (bid % 9 == 0) {
        // ================= tf32 MMA GEMM path =================
        int gidx = bid / 9;                 // 0..263
        int bm = (gidx >> 3) * 64;          // 33 row tiles
        int bn = (gidx & 7) * 64;           // 8 col tiles
        uint32_t* As = (uint32_t*)smem_raw;                 // [64][AS_STRIDE] tf32
        uint32_t* Bs = As + 64 * AS_STRIDE;                 // [32][BS_STRIDE] tf32
        int warp = tid >> 5, lane = tid & 31;
        int wr = warp >> 2;                 // 0..1 : 32-row slab
        int wc = warp & 3;                  // 0..3 : 16-col slab

        float acc[2][2][4] = {};            // (ti 16-row, tj 8-col) m16n8 frags

        for (int k0 = 0; k0 < NFEAT; k0 += 32) {
            // stage A: 64 rows x 32 k (tf32), gathered rows of X
            #pragma unroll
            for (int r = 0; r < 2; r++) {
                int f = tid + r * 256;          // 0..511
                int m = f >> 3, c4 = f & 7;
                int k = k0 + c4 * 4;
                float4 v = make_float4(0.f, 0.f, 0.f, 0.f);
                if (k < NFEAT) {
                    int gr = bm + m;
                    int node = (gr < NACT) ? act[gr] : nb[gr - NACT];
                    v = *(const float4*)(X + (size_t)node * NFEAT + k);
                }
                uint4 u = make_uint4(f2tf(v.x), f2tf(v.y), f2tf(v.z), f2tf(v.w));
                *(uint4*)&As[m * AS_STRIDE + c4 * 4] = u;
            }
            // stage B: 32 k x 64 cols (tf32)
            #pragma unroll
            for (int r = 0; r < 2; r++) {
                int f = tid + r * 256;          // 0..511
                int kr = f >> 4, c4 = f & 15;
                int k = k0 + kr;
                float4 v = make_float4(0.f, 0.f, 0.f, 0.f);
                if (k < NFEAT) v = *(const float4*)(W1 + (size_t)k * NHID + bn + c4 * 4);
                uint4 u = make_uint4(f2tf(v.x), f2tf(v.y), f2tf(v.z), f2tf(v.w));
                *(uint4*)&Bs[kr * BS_STRIDE + c4 * 4] = u;
            }
            __syncthreads();
            #pragma unroll
            for (int kk = 0; kk < 32; kk += 8) {
                uint32_t a[2][4], b[2][2];
                #pragma unroll
                for (int ti = 0; ti < 2; ti++) {
                    int r0 = wr * 32 + ti * 16 + (lane >> 2);
                    int kc = kk + (lane & 3);
                    a[ti][0] = As[r0 * AS_STRIDE + kc];
                    a[ti][1] = As[(r0 + 8) * AS_STRIDE + kc];
                    a[ti][2] = As[r0 * AS_STRIDE + kc + 4];
                    a[ti][3] = As[(r0 + 8) * AS_STRIDE + kc + 4];
                }
                #pragma unroll
                for (int tj = 0; tj < 2; tj++) {
                    int col = wc * 16 + tj * 8 + (lane >> 2);
                    int kc = kk + (lane & 3);
                    b[tj][0] = Bs[kc * BS_STRIDE + col];
                    b[tj][1] = Bs[(kc + 4) * BS_STRIDE + col];
                }
                #pragma unroll
                for (int ti = 0; ti < 2; ti++)
                    #pragma unroll
                    for (int tj = 0; tj < 2; tj++)
                        mma_tf32(acc[ti][tj], a[ti], b[tj]);
            }
            __syncthreads();
        }
        // epilogue
        int lane4 = (tid & 31) >> 2, lm = (tid & 3) * 2;
        #pragma unroll
        for (int ti = 0; ti < 2; ti++) {
            int row0 = bm + wr * 32 + ti * 16 + lane4;
            #pragma unroll
            for (int tj = 0; tj < 2; tj++) {
                int col0 = bn + wc * 16 + tj * 8 + lm;
                float* c = acc[ti][tj];
                *(float2*)&g_XW1[(size_t)row0 * NHID + col0]       = make_float2(c[0], c[1]);
                *(float2*)&g_XW1[(size_t)(row0 + 8) * NHID + col0] = make_float2(c[2], c[3]);
            }
        }
    } else {
        // ================= extract path: stream one adjacency row =================
        int i = bid - bid / 9 - 1;          // 0..2111
        int* s_cols   = (int*)smem_raw;
        int* s_sorted = s_cols + MAXNNZ;
        int* s_cntp   = s_sorted + MAXNNZ;
        if (tid == 0) *s_cntp = 0;
        __syncthreads();
        int node = (i < NACT) ? act[i] : nb[i - NACT];
        const float4* row = (const float4*)(adj + (size_t)node * NNODES);
        #pragma unroll 4
        for (int it = 0; it < NNODES / 4 / 256; it++) {
            int p = it * 256 + tid;
            float4 v = __ldcs(row + p);
            if (v.x != 0.f || v.y != 0.f || v.z != 0.f || v.w != 0.f) {
                float e[4] = {v.x, v.y, v.z, v.w};
                #pragma unroll
                for (int q = 0; q < 4; q++) {
                    if (e[q] != 0.f) {
                        int col = p * 4 + q;
                        int lov = g_loE[col];
                        if (lov > 0) {                     // col in subgraph
                            int lo = SS - lov;
                            int k = atomicAdd(s_cntp, 1);
                            if (k < MAXNNZ) s_cols[k] = lo;
                            int hi = g_hiE[col] - 1;
                            if (hi != lo) {                // wrap-pad duplicate
                                k = atomicAdd(s_cntp, 1);
                                if (k < MAXNNZ) s_cols[k] = hi;
                            }
                        }
                    }
                }
            }
        }
        __syncthreads();
        int n = min(*s_cntp, MAXNNZ);
        if (tid < n) {                       // rank-sort (values distinct)
            int val = s_cols[tid];
            int rank = 0;
            for (int k = 0; k < n; k++) rank += (s_cols[k] < val);
            s_sorted[rank] = val;
        }
        __syncthreads();
        if (tid == 0) g_nnz[i] = n;
        if (tid < n) g_cols[i * MAXNNZ + tid] = s_sorted[tid];
    }
}

// layer2: u[i] = relu(sum over sparse row of XW1) . w  — batched gathers for MLP
__global__ void k_layer2() {
    __shared__ float s_w[NHID];
    __shared__ float s_red[8];
    int i = blockIdx.x, tid = threadIdx.x;
    s_w[tid] = g_w[tid];
    s_w[tid + 256] = g_w[tid + 256];
    __syncthreads();
    int nnz = g_nnz[i];
    const int* cp = g_cols + i * MAXNNZ;
    float a0 = 0.f, a1 = 0.f;
    for (int k0 = 0; k0 < nnz; k0 += 8) {
        float v0[8], v1[8];
        #pragma unroll
        for (int q = 0; q < 8; q++) {
            float x0 = 0.f, x1 = 0.f;
            int kk = k0 + q;
            if (kk < nnz) {
                const float* s = g_XW1 + (size_t)cp[kk] * NHID;
                x0 = s[tid];
                x1 = s[tid + 256];
            }
            v0[q] = x0; v1[q] = x1;
        }
        #pragma unroll
        for (int q = 0; q < 8; q++) { a0 += v0[q]; a1 += v1[q]; }
    }
    float p = fmaxf(a0, 0.f) * s_w[tid] + fmaxf(a1, 0.f) * s_w[tid + 256];
    p = warp_sum(p);
    if ((tid & 31) == 0) s_red[tid >> 5] = p;
    __syncthreads();
    if (tid == 0) {
        float s = 0.f;
        #pragma unroll
        for (int w = 0; w < 8; w++) s += s_red[w];
        g_u[i] = s;
    }
}

// single block: v = A@u; imp = A@v + b; L1-normalize; write outputs.
// Latency-optimized: u and v staged in shared (gathers become LDS), column
// lists loaded as int4 (4 cols per transaction, independent across rows).
__global__ void k_finalize(const float* __restrict__ impb, const int* __restrict__ nb,
                           float* __restrict__ out, int out_size) {
    __shared__ float s_u[SS];
    __shared__ float s_v[SS];
    __shared__ float s_imp[SS];
    __shared__ float s_red[32];
    __shared__ float s_tot;
    int tid = threadIdx.x;

    // stage u coalesced
    for (int j = tid; j < SS; j += 1024) s_u[j] = g_u[j];
    __syncthreads();

    // pass 1: v = A @ u   (gathers from shared; int4 column loads)
    for (int i = tid; i < SS; i += 1024) {
        int nnz = g_nnz[i];
        const int4* cp4 = (const int4*)(g_cols + i * MAXNNZ);   // 256B-aligned rows
        float a = 0.f;
        for (int k0 = 0; k0 < nnz; k0 += 4) {
            int4 c = cp4[k0 >> 2];
            if (k0 + 0 < nnz) a += s_u[c.x];
            if (k0 + 1 < nnz) a += s_u[c.y];
            if (k0 + 2 < nnz) a += s_u[c.z];
            if (k0 + 3 < nnz) a += s_u[c.w];
        }
        s_v[i] = a;
    }
    __syncthreads();

    // pass 2: imp = A @ v + b ; accumulate L1 norm
    float b = impb[0];
    float part = 0.f;
    for (int i = tid; i < SS; i += 1024) {
        int nnz = g_nnz[i];
        const int4* cp4 = (const int4*)(g_cols + i * MAXNNZ);
        float a = b;
        for (int k0 = 0; k0 < nnz; k0 += 4) {
            int4 c = cp4[k0 >> 2];
            if (k0 + 0 < nnz) a += s_v[c.x];
            if (k0 + 1 < nnz) a += s_v[c.y];
            if (k0 + 2 < nnz) a += s_v[c.z];
            if (k0 + 3 < nnz) a += s_v[c.w];
        }
        s_imp[i] = a;
        part += fabsf(a);
    }
    part = warp_sum(part);
    if ((tid & 31) == 0) s_red[tid >> 5] = part;
    __syncthreads();
    if (tid == 0) {
        float s = 0.f;
        #pragma unroll
        for (int w = 0; w < 32; w++) s += s_red[w];
        s_tot = s;
    }
    __syncthreads();
    float inv = 1.f / fmaxf(s_tot, 1e-12f);
    for (int j = tid; j < NEIGH; j += 1024) out[j] = s_imp[NACT + j] * inv;
    if (out_size >= 2 * NEIGH)
        for (int j = tid; j < NEIGH; j += 1024) out[NEIGH + j] = (float)nb[j];
}

extern "C" void kernel_launch(void* const* d_in, const int* in_sizes, int n_in,
                              void* d_out, int out_size) {
    const float* x   = (const float*)d_in[0];
    const float* adj = (const float*)d_in[1];
    const int*   act = (const int*)d_in[2];
    const int*   nb  = (const int*)d_in[3];
    const float* W1  = (const float*)d_in[4];
    const float* W2  = (const float*)d_in[5];
    const float* iw  = (const float*)d_in[6];
    const float* ib  = (const float*)d_in[7];
    float* out = (float*)d_out;
    (void)in_sizes; (void)n_in;

    k_prep<<<NNODES / 256, 256>>>(act, nb, W2, iw);
    k_main<<<MAIN_BLOCKS, 256>>>(x, W1, adj, act, nb);
    k_layer2<<<SS, 256>>>();
    k_finalize<<<1, 1024>>>(ib, nb, out, out_size);
}